// round 16
// baseline (speedup 1.0000x reference)
#include <cuda_runtime.h>
#include <cuda_fp16.h>
#include <cstdint>
#include <math.h>

#define S_  2048
#define D_  4096
#define H_  32
#define HD_ 128
#define FF_ 11008
#define QKVS (3 * D_)    // 12288 row stride of merged qkv
#define GUS  (2 * FF_)   // 22016 interleaved gate|up weight rows

// ---------------- scratch (no allocations allowed) ----------------
__device__ float g_x2 [(size_t)S_ * D_];

__device__ __half g_qkvh[(size_t)S_ * QKVS];  // [S, q|k|v]; later reused for silu output [S, FF_]
__device__ __half g_ah  [(size_t)S_ * D_];    // fp16 activation (rmsnorm out / attn out)

// transposed fp16 weights, layout [N, K] row-major (merged)
__device__ __half g_wqkvt[(size_t)QKVS * D_]; // wq|wk|wv rows
__device__ __half g_wgut [(size_t)GUS * D_];  // interleaved: row 2j = wg_j, 2j+1 = w1_j
__device__ __half g_wot  [(size_t)D_ * D_];
__device__ __half g_w2t  [(size_t)D_ * FF_];

// ---------------- asm helpers ----------------
__device__ __forceinline__ uint32_t smem_to_u32(const void* p) {
    uint32_t a;
    asm("{ .reg .u64 t; cvta.to.shared.u64 t, %1; cvt.u32.u64 %0, t; }" : "=r"(a) : "l"(p));
    return a;
}
__device__ __forceinline__ void cp16(uint32_t saddr, const void* gaddr) {
    asm volatile("cp.async.cg.shared.global [%0], [%1], 16;" :: "r"(saddr), "l"(gaddr));
}
#define CP_COMMIT() asm volatile("cp.async.commit_group;" ::: "memory")
#define CP_WAIT(n)  asm volatile("cp.async.wait_group %0;" :: "n"(n) : "memory")

#define LDSM_X4(r0, r1, r2, r3, addr) \
    asm volatile("ldmatrix.sync.aligned.m8n8.x4.shared.b16 {%0,%1,%2,%3}, [%4];" \
        : "=r"(r0), "=r"(r1), "=r"(r2), "=r"(r3) : "r"(addr))
#define LDSM_X4_T(r0, r1, r2, r3, addr) \
    asm volatile("ldmatrix.sync.aligned.m8n8.x4.trans.shared.b16 {%0,%1,%2,%3}, [%4];" \
        : "=r"(r0), "=r"(r1), "=r"(r2), "=r"(r3) : "r"(addr))

#define MMA16816(d, a, b) \
    asm volatile("mma.sync.aligned.m16n8k16.row.col.f32.f16.f16.f32 " \
        "{%0,%1,%2,%3}, {%4,%5,%6,%7}, {%8,%9}, {%0,%1,%2,%3};" \
        : "+f"((d)[0]), "+f"((d)[1]), "+f"((d)[2]), "+f"((d)[3]) \
        : "r"((a)[0]), "r"((a)[1]), "r"((a)[2]), "r"((a)[3]), "r"((b)[0]), "r"((b)[1]))
#define MMA4(d, a0, a1, a2, a3, b0, b1) \
    asm volatile("mma.sync.aligned.m16n8k16.row.col.f32.f16.f16.f32 " \
        "{%0,%1,%2,%3}, {%4,%5,%6,%7}, {%8,%9}, {%0,%1,%2,%3};" \
        : "+f"((d)[0]), "+f"((d)[1]), "+f"((d)[2]), "+f"((d)[3]) \
        : "r"(a0), "r"(a1), "r"(a2), "r"(a3), "r"(b0), "r"(b1))

__device__ __forceinline__ uint32_t packh(__half a, __half b) {
    return ((uint32_t)__half_as_ushort(b) << 16) | __half_as_ushort(a);
}
__device__ __forceinline__ uint4 cvt8h(const float* v) {
    uint32_t hh[4];
    #pragma unroll
    for (int j = 0; j < 4; j++)
        hh[j] = packh(__float2half_rn(v[2 * j]), __float2half_rn(v[2 * j + 1]));
    return make_uint4(hh[0], hh[1], hh[2], hh[3]);
}

// ---------------- weight transpose: 64(k) x 32(n) tile, uint4 writes, row remap ----------------
__global__ __launch_bounds__(256) void wconv2_kernel(
    const float* __restrict__ W, __half* __restrict__ Wh, int K, int N, float scale,
    int rstride, int roff)
{
    __shared__ float t[64][33];
    int n0 = blockIdx.x * 32, k0 = blockIdx.y * 64;
    int tid = threadIdx.x;
    int nloc = tid & 31, kr = tid >> 5;
    #pragma unroll
    for (int i = 0; i < 8; i++)
        t[kr * 8 + i][nloc] = W[(size_t)(k0 + kr * 8 + i) * N + n0 + nloc];
    __syncthreads();
    int nr = tid >> 3, kc = (tid & 7) << 3;
    float vv[8];
    #pragma unroll
    for (int j = 0; j < 8; j++) vv[j] = t[kc + j][nr] * scale;
    *(uint4*)(Wh + (size_t)((n0 + nr) * rstride + roff) * K + k0 + kc) = cvt8h(vv);
}

// ---------------- HMMA GEMM: plain fp16, CTA 128x128, BK=64, 3-stage, 2 CTA/SM ----------------
// MODE 0: fp32 out + residual.
// MODE 2: silu-pair (interleaved gate|up cols -> silu(g)*u into [M, FF_] fp16).
// MODE 3: fp16 out with fused RoPE on cols < 2*D_ (merged qkv).
#define STAGES 3
#define OPBYTES 16384
#define STAGE_BYTES (2 * OPBYTES)
#define HGEMM_SMEM (STAGES * STAGE_BYTES)   // 96KB -> 2 CTAs/SM

template <int MODE>
__global__ __launch_bounds__(256, 2) void hgemm(
    int M, int N, int K,
    const __half* __restrict__ A, const __half* __restrict__ B,
    const float* __restrict__ Rsd, void* __restrict__ Cv)
{
    extern __shared__ __align__(1024) char smem[];
    const int tid  = threadIdx.x;
    const int wid  = tid >> 5;
    const int lane = tid & 31;
    const int m0 = blockIdx.x * 128;
    const int n0 = blockIdx.y * 128;
    const int nk = K >> 6;
    const uint32_t sbase = smem_to_u32(smem);

    const int wm = (wid & 3) * 32;
    const int wn = (wid >> 2) * 64;

    const __half* Abase = A + (size_t)m0 * K;
    const __half* Bbase = B + (size_t)n0 * K;

    int lrow[4], lcc[4];
    uint32_t lsoff[4];
    #pragma unroll
    for (int t = 0; t < 4; t++) {
        int c = tid + t * 256;
        lrow[t] = c >> 3;
        lcc[t]  = c & 7;
        lsoff[t] = lrow[t] * 128 + (((lcc[t] ^ (lrow[t] & 7))) << 4);
    }

    #define ISSUE(s, kt) do { \
        uint32_t sb_ = sbase + (s) * STAGE_BYTES; \
        size_t kofs_ = (size_t)(kt) << 6; \
        _Pragma("unroll") \
        for (int t = 0; t < 4; t++) { \
            size_t go_ = (size_t)lrow[t] * K + kofs_ + lcc[t] * 8; \
            uint32_t so_ = sb_ + lsoff[t]; \
            cp16(so_,           Abase + go_); \
            cp16(so_ + OPBYTES, Bbase + go_); \
        } \
    } while (0)

    float acc[2][8][4] = {};

    #pragma unroll
    for (int s = 0; s < STAGES - 1; s++) { ISSUE(s, s); CP_COMMIT(); }

    const int mat = lane >> 3, rin = lane & 7;

    for (int i = 0; i < nk; i++) {
        CP_WAIT(STAGES - 2);
        __syncthreads();
        if (i + STAGES - 1 < nk) { ISSUE((i + STAGES - 1) % STAGES, i + STAGES - 1); }
        CP_COMMIT();

        uint32_t stg = sbase + (i % STAGES) * STAGE_BYTES;
        #pragma unroll
        for (int ks = 0; ks < 4; ks++) {
            int ks2 = ks << 1;
            uint32_t fa[2][4], fb[8][2];
            #pragma unroll
            for (int mt = 0; mt < 2; mt++) {
                int m = wm + mt * 16 + ((mat & 1) << 3) + rin;
                uint32_t ad = stg + m * 128 + (((ks2 + (mat >> 1)) ^ (m & 7)) << 4);
                LDSM_X4(fa[mt][0], fa[mt][1], fa[mt][2], fa[mt][3], ad);
            }
            #pragma unroll
            for (int p = 0; p < 4; p++) {
                int n = wn + p * 16 + ((mat >> 1) << 3) + rin;
                uint32_t bd = stg + OPBYTES + n * 128 + (((ks2 + (mat & 1)) ^ (n & 7)) << 4);
                uint32_t r0, r1, r2, r3;
                LDSM_X4(r0, r1, r2, r3, bd);
                fb[p * 2][0] = r0; fb[p * 2][1] = r1;
                fb[p * 2 + 1][0] = r2; fb[p * 2 + 1][1] = r3;
            }
            #pragma unroll
            for (int mt = 0; mt < 2; mt++)
                #pragma unroll
                for (int nt = 0; nt < 8; nt++)
                    MMA16816(acc[mt][nt], fa[mt], fb[nt]);
        }
        __syncthreads();
    }
    #undef ISSUE

    int qr = lane >> 2, qc = (lane & 3) << 1;
    #pragma unroll
    for (int mt = 0; mt < 2; mt++) {
        #pragma unroll
        for (int nt = 0; nt < 8; nt++) {
            int r0 = m0 + wm + mt * 16 + qr;
            int cc = n0 + wn + nt * 8 + qc;
            float a0 = acc[mt][nt][0], a1 = acc[mt][nt][1];
            float a2 = acc[mt][nt][2], a3 = acc[mt][nt][3];
            if (MODE == 0) {
                float* C = (float*)Cv;
                float2 ra = *(const float2*)(Rsd + (size_t)r0 * N + cc);
                float2 rb = *(const float2*)(Rsd + (size_t)(r0 + 8) * N + cc);
                *(float2*)(C + (size_t)r0 * N + cc)       = make_float2(a0 + ra.x, a1 + ra.y);
                *(float2*)(C + (size_t)(r0 + 8) * N + cc) = make_float2(a2 + rb.x, a3 + rb.y);
            } else if (MODE == 2) {
                __half* Ch = (__half*)Cv;
                int j = cc >> 1;
                float h0 = a0 / (1.f + __expf(-a0)) * a1;
                float h1 = a2 / (1.f + __expf(-a2)) * a3;
                Ch[(size_t)r0 * FF_ + j]       = __float2half_rn(h0);
                Ch[(size_t)(r0 + 8) * FF_ + j] = __float2half_rn(h1);
            } else {
                if (MODE == 3 && cc < 2 * D_) {
                    int j = (cc & (HD_ - 1)) >> 1;
                    float invf = (float)exp((double)j * -0.14391156831212787);
                    float sn, cs;
                    sincosf((float)r0 * invf, &sn, &cs);
                    float t0 = a0 * cs - a1 * sn, t1 = a0 * sn + a1 * cs;
                    a0 = t0; a1 = t1;
                    sincosf((float)(r0 + 8) * invf, &sn, &cs);
                    t0 = a2 * cs - a3 * sn; t1 = a2 * sn + a3 * cs;
                    a2 = t0; a3 = t1;
                }
                __half* Ch = (__half*)Cv;
                *reinterpret_cast<uint32_t*>(Ch + (size_t)r0 * N + cc) =
                    packh(__float2half_rn(a0), __float2half_rn(a1));
                *reinterpret_cast<uint32_t*>(Ch + (size_t)(r0 + 8) * N + cc) =
                    packh(__float2half_rn(a2), __float2half_rn(a3));
            }
        }
    }
}

// ---------------- RMSNorm with fused fp16 output ----------------
__global__ __launch_bounds__(256) void rmsnorm_h_kernel(
    const float* __restrict__ x, const float* __restrict__ w, __half* __restrict__ oh)
{
    int row = blockIdx.x;
    const float4* xr = (const float4*)(x + (size_t)row * D_);
    float ss = 0.f;
    #pragma unroll 4
    for (int i = threadIdx.x; i < D_ / 4; i += 256) {
        float4 v = xr[i];
        ss += v.x * v.x + v.y * v.y + v.z * v.z + v.w * v.w;
    }
    __shared__ float red[8];
    #pragma unroll
    for (int o = 16; o; o >>= 1) ss += __shfl_xor_sync(0xffffffffu, ss, o);
    if ((threadIdx.x & 31) == 0) red[threadIdx.x >> 5] = ss;
    __syncthreads();
    if (threadIdx.x == 0) {
        float t = 0.f;
        #pragma unroll
        for (int i = 0; i < 8; i++) t += red[i];
        red[0] = rsqrtf(t / (float)D_ + 1e-5f);
    }
    __syncthreads();
    float inv = red[0];
    const float4* wr = (const float4*)w;
    for (int i = threadIdx.x; i < D_ / 8; i += 256) {
        float vv[8];
        float4 a = xr[2 * i], b = xr[2 * i + 1];
        float4 wa = wr[2 * i], wb = wr[2 * i + 1];
        vv[0] = a.x * inv * wa.x; vv[1] = a.y * inv * wa.y;
        vv[2] = a.z * inv * wa.z; vv[3] = a.w * inv * wa.w;
        vv[4] = b.x * inv * wb.x; vv[5] = b.y * inv * wb.y;
        vv[6] = b.z * inv * wb.z; vv[7] = b.w * inv * wb.w;
        ((uint4*)(oh + (size_t)row * D_))[i] = cvt8h(vv);
    }
}

// ---------------- HMMA flash attention: fp16 in/out, 1-term, double-buffered KV ----------------
#define ATQ 0
#define ATK(b) (32768 + (b) * 32768)
#define ATV(b) (ATK(b) + 16384)
#define ATTN3_SMEM 98304

__global__ __launch_bounds__(256, 1) void attn3_kernel(
    const __half* __restrict__ QKV, __half* __restrict__ Oh)
{
    extern __shared__ __align__(1024) char sm2[];
    const uint32_t sb = smem_to_u32(sm2);
    const int tid = threadIdx.x, wid = tid >> 5, lane = tid & 31;
    const int h = blockIdx.y;
    const int bq = gridDim.x - 1 - blockIdx.x;
    const int q0 = bq * 128;
    const int mat = lane >> 3, rin = lane & 7;

    const __half* Q  = QKV;
    const __half* Kg = QKV + D_;
    const __half* Vg = QKV + 2 * D_;

    #pragma unroll
    for (int i = 0; i < 8; i++) {
        int idx = tid + i * 256;
        int row = idx >> 4, cc = idx & 15;
        cp16(sb + ATQ + row * 256 + ((cc ^ (row & 7)) << 4),
             Q + (size_t)(q0 + row) * QKVS + h * HD_ + cc * 8);
    }
    CP_COMMIT();

    #define ISSUEKV(b, kt) do { \
        int k0_ = (kt) * 64; \
        _Pragma("unroll") \
        for (int i_ = 0; i_ < 4; i_++) { \
            int idx_ = tid + i_ * 256; \
            int row_ = idx_ >> 4, cc_ = idx_ & 15; \
            uint32_t off_ = row_ * 256 + ((cc_ ^ (row_ & 7)) << 4); \
            cp16(sb + ATK(b) + off_, Kg + (size_t)(k0_ + row_) * QKVS + h * HD_ + cc_ * 8); \
            cp16(sb + ATV(b) + off_, Vg + (size_t)(k0_ + row_) * QKVS + h * HD_ + cc_ * 8); \
        } \
    } while (0)

    const int nk = q0 / 64 + 2;
    ISSUEKV(0, 0); CP_COMMIT();

    float m0 = -1e30f, m1 = -1e30f, l0 = 0.f, l1 = 0.f;
    float oacc[16][4] = {};
    const int g0r = q0 + wid * 16 + (lane >> 2);
    const int g1r = g0r + 8;

    for (int kt = 0; kt < nk; kt++) {
        if (kt + 1 < nk) { ISSUEKV((kt + 1) & 1, kt + 1); CP_COMMIT(); CP_WAIT(1); }
        else            { CP_WAIT(0); }
        __syncthreads();
        int k0 = kt * 64;
        int buf = kt & 1;

        float sacc[8][4] = {};
        #pragma unroll
        for (int kk = 0; kk < 8; kk++) {
            int kk2 = kk << 1;
            int m = wid * 16 + ((mat & 1) << 3) + rin;
            uint32_t ad = sb + ATQ + m * 256 + (((kk2 + (mat >> 1)) ^ (m & 7)) << 4);
            uint32_t qa[4];
            LDSM_X4(qa[0], qa[1], qa[2], qa[3], ad);
            #pragma unroll
            for (int nt = 0; nt < 4; nt++) {
                int n = nt * 16 + ((mat >> 1) << 3) + rin;
                uint32_t bd = sb + ATK(buf) + n * 256 + (((kk2 + (mat & 1)) ^ (n & 7)) << 4);
                uint32_t b0, b1, b2, b3;
                LDSM_X4(b0, b1, b2, b3, bd);
                MMA4(sacc[2 * nt],     qa[0], qa[1], qa[2], qa[3], b0, b1);
                MMA4(sacc[2 * nt + 1], qa[0], qa[1], qa[2], qa[3], b2, b3);
            }
        }

        if (k0 + 63 > g0r) {
            #pragma unroll
            for (int nt = 0; nt < 8; nt++) {
                int c0 = k0 + nt * 8 + ((lane & 3) << 1);
                if (c0     > g0r) sacc[nt][0] = -1e30f;
                if (c0 + 1 > g0r) sacc[nt][1] = -1e30f;
                if (c0     > g1r) sacc[nt][2] = -1e30f;
                if (c0 + 1 > g1r) sacc[nt][3] = -1e30f;
            }
        }

        float mx0 = m0, mx1 = m1;
        #pragma unroll
        for (int nt = 0; nt < 8; nt++) {
            mx0 = fmaxf(mx0, fmaxf(sacc[nt][0], sacc[nt][1]));
            mx1 = fmaxf(mx1, fmaxf(sacc[nt][2], sacc[nt][3]));
        }
        mx0 = fmaxf(mx0, __shfl_xor_sync(0xffffffffu, mx0, 1));
        mx0 = fmaxf(mx0, __shfl_xor_sync(0xffffffffu, mx0, 2));
        mx1 = fmaxf(mx1, __shfl_xor_sync(0xffffffffu, mx1, 1));
        mx1 = fmaxf(mx1, __shfl_xor_sync(0xffffffffu, mx1, 2));
        float al0 = __expf(m0 - mx0), al1 = __expf(m1 - mx1);
        m0 = mx0; m1 = mx1;
        float rs0 = 0.f, rs1 = 0.f;
        uint32_t ph0[8], ph1[8];
        #pragma unroll
        for (int nt = 0; nt < 8; nt++) {
            float p0 = __expf(sacc[nt][0] - mx0);
            float p1 = __expf(sacc[nt][1] - mx0);
            float p2 = __expf(sacc[nt][2] - mx1);
            float p3 = __expf(sacc[nt][3] - mx1);
            rs0 += p0 + p1; rs1 += p2 + p3;
            ph0[nt] = packh(__float2half_rn(p0), __float2half_rn(p1));
            ph1[nt] = packh(__float2half_rn(p2), __float2half_rn(p3));
        }
        rs0 += __shfl_xor_sync(0xffffffffu, rs0, 1);
        rs0 += __shfl_xor_sync(0xffffffffu, rs0, 2);
        rs1 += __shfl_xor_sync(0xffffffffu, rs1, 1);
        rs1 += __shfl_xor_sync(0xffffffffu, rs1, 2);
        l0 = l0 * al0 + rs0;
        l1 = l1 * al1 + rs1;
        #pragma unroll
        for (int t = 0; t < 16; t++) {
            oacc[t][0] *= al0; oacc[t][1] *= al0;
            oacc[t][2] *= al1; oacc[t][3] *= al1;
        }

        #pragma unroll
        for (int kk = 0; kk < 4; kk++) {
            uint32_t a0 = ph0[2 * kk], a1 = ph1[2 * kk], a2 = ph0[2 * kk + 1], a3 = ph1[2 * kk + 1];
            #pragma unroll
            for (int ntp = 0; ntp < 8; ntp++) {
                int vrow = kk * 16 + rin + ((mat >> 1) << 3);
                int vch  = 2 * ntp + (mat & 1);
                uint32_t vd = sb + ATV(buf) + vrow * 256 + ((vch ^ (vrow & 7)) << 4);
                uint32_t r0, r1, r2, r3;
                LDSM_X4_T(r0, r1, r2, r3, vd);
                MMA4(oacc[2 * ntp],     a0, a1, a2, a3, r0, r2);
                MMA4(oacc[2 * ntp + 1], a0, a1, a2, a3, r1, r3);
            }
        }
        __syncthreads();
    }
    #undef ISSUEKV

    float i0 = 1.f / l0, i1 = 1.f / l1;
    #pragma unroll
    for (int t = 0; t < 16; t++) {
        int col = h * HD_ + t * 8 + ((lane & 3) << 1);
        *reinterpret_cast<uint32_t*>(Oh + (size_t)g0r * D_ + col) =
            packh(__float2half_rn(oacc[t][0] * i0), __float2half_rn(oacc[t][1] * i0));
        *reinterpret_cast<uint32_t*>(Oh + (size_t)g1r * D_ + col) =
            packh(__float2half_rn(oacc[t][2] * i1), __float2half_rn(oacc[t][3] * i1));
    }
}

// ---------------- launch ----------------
extern "C" void kernel_launch(void* const* d_in, const int* in_sizes, int n_in,
                              void* d_out, int out_size)
{
    const float* x      = (const float*)d_in[0];
    const float* ln_w   = (const float*)d_in[1];
    const float* ffln_w = (const float*)d_in[2];
    const float* wq     = (const float*)d_in[3];
    const float* wk     = (const float*)d_in[4];
    const float* wv     = (const float*)d_in[5];
    const float* wo     = (const float*)d_in[6];
    const float* wg     = (const float*)d_in[7];
    const float* w1     = (const float*)d_in[8];
    const float* w2     = (const float*)d_in[9];
    float* out = (float*)d_out;

    float* x2;
    cudaGetSymbolAddress((void**)&x2, g_x2);

    __half *qkvh, *ah;
    cudaGetSymbolAddress((void**)&qkvh, g_qkvh);
    cudaGetSymbolAddress((void**)&ah,   g_ah);

    __half *wqkvt, *wgut, *wot, *w2t;
    cudaGetSymbolAddress((void**)&wqkvt, g_wqkvt);
    cudaGetSymbolAddress((void**)&wgut,  g_wgut);
    cudaGetSymbolAddress((void**)&wot,   g_wot);
    cudaGetSymbolAddress((void**)&w2t,   g_w2t);

    cudaFuncSetAttribute(attn3_kernel, cudaFuncAttributeMaxDynamicSharedMemorySize, ATTN3_SMEM);
    cudaFuncSetAttribute(hgemm<0>, cudaFuncAttributeMaxDynamicSharedMemorySize, HGEMM_SMEM);
    cudaFuncSetAttribute(hgemm<2>, cudaFuncAttributeMaxDynamicSharedMemorySize, HGEMM_SMEM);
    cudaFuncSetAttribute(hgemm<3>, cudaFuncAttributeMaxDynamicSharedMemorySize, HGEMM_SMEM);

    // weight prep into merged buffers (wq carries 1/sqrt(HD); wg/w1 interleaved)
    const float qscale = 0.08838834764831845f;
    wconv2_kernel<<<dim3(D_ / 32, D_ / 64), 256>>>(wq, wqkvt,                       D_, D_, qscale, 1, 0);
    wconv2_kernel<<<dim3(D_ / 32, D_ / 64), 256>>>(wk, wqkvt + (size_t)D_ * D_,     D_, D_, 1.f,    1, 0);
    wconv2_kernel<<<dim3(D_ / 32, D_ / 64), 256>>>(wv, wqkvt + (size_t)2 * D_ * D_, D_, D_, 1.f,    1, 0);
    wconv2_kernel<<<dim3(D_ / 32, D_ / 64), 256>>>(wo, wot, D_, D_, 1.f, 1, 0);
    wconv2_kernel<<<dim3(FF_ / 32, D_ / 64), 256>>>(wg, wgut, D_, FF_, 1.f, 2, 0);
    wconv2_kernel<<<dim3(FF_ / 32, D_ / 64), 256>>>(w1, wgut, D_, FF_, 1.f, 2, 1);
    wconv2_kernel<<<dim3(D_ / 32, FF_ / 64), 256>>>(w2, w2t, FF_, D_, 1.f, 1, 0);

    // xn = rmsnorm(x) -> ah
    rmsnorm_h_kernel<<<S_, 256>>>(x, ln_w, ah);

    // merged qkv projection with fused RoPE (one N=12288 GEMM)
    hgemm<3><<<dim3(S_ / 128, QKVS / 128), 256, HGEMM_SMEM>>>(
        S_, QKVS, D_, ah, wqkvt, nullptr, qkvh);

    // attention (O -> ah)
    attn3_kernel<<<dim3(S_ / 128, H_), 256, ATTN3_SMEM>>>(qkvh, ah);

    // x2 = attn @ wo + x   (fp32 out)
    hgemm<0><<<dim3(S_ / 128, D_ / 128), 256, HGEMM_SMEM>>>(
        S_, D_, D_, ah, wot, x, x2);

    // xn2 = rmsnorm(x2) -> ah
    rmsnorm_h_kernel<<<S_, 256>>>(x2, ffln_w, ah);

    // merged gate|up projection with fused SiLU -> qkvh (dead buffer, [S, FF_])
    hgemm<2><<<dim3(S_ / 128, GUS / 128), 256, HGEMM_SMEM>>>(
        S_, GUS, D_, ah, wgut, nullptr, qkvh);

    // out = h @ w2 + x2  (fp32 out)
    hgemm<0><<<dim3(S_ / 128, D_ / 128), 256, HGEMM_SMEM>>>(
        S_, D_, FF_, qkvh, w2t, x2, out);
}

// round 17
// speedup vs baseline: 1.5586x; 1.5586x over previous
#include <cuda_runtime.h>
#include <cuda_fp16.h>
#include <cstdint>
#include <math.h>

#define S_  2048
#define D_  4096
#define H_  32
#define HD_ 128
#define FF_ 11008
#define QKVS (3 * D_)    // 12288 row stride of merged qkv
#define GUS  (2 * FF_)   // 22016 row stride of merged gate|up

// ---------------- scratch (no allocations allowed) ----------------
__device__ float g_x2 [(size_t)S_ * D_];

__device__ __half g_qkvh[(size_t)S_ * QKVS];  // [S, q|k|v] (rope applied in GEMM epilogue)
__device__ __half g_guh [(size_t)S_ * GUS];   // [S, gate|up]
__device__ __half g_ah  [(size_t)S_ * FF_];   // activation input to GEMMs

// transposed fp16 weights, layout [N, K] row-major (merged)
__device__ __half g_wqkvt[(size_t)QKVS * D_]; // wq|wk|wv rows
__device__ __half g_wgut [(size_t)GUS * D_];  // wg|w1 rows
__device__ __half g_wot  [(size_t)D_ * D_];
__device__ __half g_w2t  [(size_t)D_ * FF_];

// fp64-accurate inv_freq table (fp32 storage)
__device__ float g_invf[HD_ / 2];

// ---------------- asm helpers ----------------
__device__ __forceinline__ uint32_t smem_to_u32(const void* p) {
    uint32_t a;
    asm("{ .reg .u64 t; cvta.to.shared.u64 t, %1; cvt.u32.u64 %0, t; }" : "=r"(a) : "l"(p));
    return a;
}
__device__ __forceinline__ void cp16(uint32_t saddr, const void* gaddr) {
    asm volatile("cp.async.cg.shared.global [%0], [%1], 16;" :: "r"(saddr), "l"(gaddr));
}
#define CP_COMMIT() asm volatile("cp.async.commit_group;" ::: "memory")
#define CP_WAIT(n)  asm volatile("cp.async.wait_group %0;" :: "n"(n) : "memory")

#define LDSM_X4(r0, r1, r2, r3, addr) \
    asm volatile("ldmatrix.sync.aligned.m8n8.x4.shared.b16 {%0,%1,%2,%3}, [%4];" \
        : "=r"(r0), "=r"(r1), "=r"(r2), "=r"(r3) : "r"(addr))
#define LDSM_X4_T(r0, r1, r2, r3, addr) \
    asm volatile("ldmatrix.sync.aligned.m8n8.x4.trans.shared.b16 {%0,%1,%2,%3}, [%4];" \
        : "=r"(r0), "=r"(r1), "=r"(r2), "=r"(r3) : "r"(addr))

#define MMA16816(d, a, b) \
    asm volatile("mma.sync.aligned.m16n8k16.row.col.f32.f16.f16.f32 " \
        "{%0,%1,%2,%3}, {%4,%5,%6,%7}, {%8,%9}, {%0,%1,%2,%3};" \
        : "+f"((d)[0]), "+f"((d)[1]), "+f"((d)[2]), "+f"((d)[3]) \
        : "r"((a)[0]), "r"((a)[1]), "r"((a)[2]), "r"((a)[3]), "r"((b)[0]), "r"((b)[1]))
#define MMA4(d, a0, a1, a2, a3, b0, b1) \
    asm volatile("mma.sync.aligned.m16n8k16.row.col.f32.f16.f16.f32 " \
        "{%0,%1,%2,%3}, {%4,%5,%6,%7}, {%8,%9}, {%0,%1,%2,%3};" \
        : "+f"((d)[0]), "+f"((d)[1]), "+f"((d)[2]), "+f"((d)[3]) \
        : "r"(a0), "r"(a1), "r"(a2), "r"(a3), "r"(b0), "r"(b1))

__device__ __forceinline__ uint32_t packh(__half a, __half b) {
    return ((uint32_t)__half_as_ushort(b) << 16) | __half_as_ushort(a);
}
__device__ __forceinline__ uint4 cvt8h(const float* v) {
    uint32_t hh[4];
    #pragma unroll
    for (int j = 0; j < 4; j++)
        hh[j] = packh(__float2half_rn(v[2 * j]), __float2half_rn(v[2 * j + 1]));
    return make_uint4(hh[0], hh[1], hh[2], hh[3]);
}

// ---------------- init: fp64-accurate inv_freq table ----------------
__global__ void rope_init_kernel()
{
    int j = threadIdx.x;   // 0..63
    g_invf[j] = (float)exp((double)j * -0.14391156831212787);
}

// ---------------- weight transpose: 64(k) x 32(n) tile, uint4 writes ----------------
__global__ __launch_bounds__(256) void wconv2_kernel(
    const float* __restrict__ W, __half* __restrict__ Wh, int K, int N, float scale)
{
    __shared__ float t[64][33];
    int n0 = blockIdx.x * 32, k0 = blockIdx.y * 64;
    int tid = threadIdx.x;
    int nloc = tid & 31, kr = tid >> 5;
    #pragma unroll
    for (int i = 0; i < 8; i++)
        t[kr * 8 + i][nloc] = W[(size_t)(k0 + kr * 8 + i) * N + n0 + nloc];
    __syncthreads();
    int nr = tid >> 3, kc = (tid & 7) << 3;
    float vv[8];
    #pragma unroll
    for (int j = 0; j < 8; j++) vv[j] = t[kc + j][nr] * scale;
    *(uint4*)(Wh + (size_t)(n0 + nr) * K + k0 + kc) = cvt8h(vv);
}

// ---------------- HMMA GEMM: plain fp16, CTA 128x128, BK=64, 3-stage, 2 CTA/SM ----------------
// MODE 0: fp32 out + residual.  MODE 1: fp16 out.  MODE 3: fp16 out, fused RoPE on cols < 2*D_.
#define STAGES 3
#define OPBYTES 16384
#define STAGE_BYTES (2 * OPBYTES)
#define HGEMM_SMEM (STAGES * STAGE_BYTES)   // 96KB -> 2 CTAs/SM

template <int MODE>
__global__ __launch_bounds__(256, 2) void hgemm(
    int M, int N, int K,
    const __half* __restrict__ A, const __half* __restrict__ B,
    const float* __restrict__ Rsd, void* __restrict__ Cv)
{
    extern __shared__ __align__(1024) char smem[];
    const int tid  = threadIdx.x;
    const int wid  = tid >> 5;
    const int lane = tid & 31;
    const int m0 = blockIdx.x * 128;
    const int n0 = blockIdx.y * 128;
    const int nk = K >> 6;
    const uint32_t sbase = smem_to_u32(smem);

    const int wm = (wid & 3) * 32;
    const int wn = (wid >> 2) * 64;

    const __half* Abase = A + (size_t)m0 * K;
    const __half* Bbase = B + (size_t)n0 * K;

    int lrow[4], lcc[4];
    uint32_t lsoff[4];
    #pragma unroll
    for (int t = 0; t < 4; t++) {
        int c = tid + t * 256;
        lrow[t] = c >> 3;
        lcc[t]  = c & 7;
        lsoff[t] = lrow[t] * 128 + (((lcc[t] ^ (lrow[t] & 7))) << 4);
    }

    #define ISSUE(s, kt) do { \
        uint32_t sb_ = sbase + (s) * STAGE_BYTES; \
        size_t kofs_ = (size_t)(kt) << 6; \
        _Pragma("unroll") \
        for (int t = 0; t < 4; t++) { \
            size_t go_ = (size_t)lrow[t] * K + kofs_ + lcc[t] * 8; \
            uint32_t so_ = sb_ + lsoff[t]; \
            cp16(so_,           Abase + go_); \
            cp16(so_ + OPBYTES, Bbase + go_); \
        } \
    } while (0)

    float acc[2][8][4] = {};

    #pragma unroll
    for (int s = 0; s < STAGES - 1; s++) { ISSUE(s, s); CP_COMMIT(); }

    const int mat = lane >> 3, rin = lane & 7;

    for (int i = 0; i < nk; i++) {
        CP_WAIT(STAGES - 2);
        __syncthreads();
        if (i + STAGES - 1 < nk) { ISSUE((i + STAGES - 1) % STAGES, i + STAGES - 1); }
        CP_COMMIT();

        uint32_t stg = sbase + (i % STAGES) * STAGE_BYTES;
        #pragma unroll
        for (int ks = 0; ks < 4; ks++) {
            int ks2 = ks << 1;
            uint32_t fa[2][4], fb[8][2];
            #pragma unroll
            for (int mt = 0; mt < 2; mt++) {
                int m = wm + mt * 16 + ((mat & 1) << 3) + rin;
                uint32_t ad = stg + m * 128 + (((ks2 + (mat >> 1)) ^ (m & 7)) << 4);
                LDSM_X4(fa[mt][0], fa[mt][1], fa[mt][2], fa[mt][3], ad);
            }
            #pragma unroll
            for (int p = 0; p < 4; p++) {
                int n = wn + p * 16 + ((mat >> 1) << 3) + rin;
                uint32_t bd = stg + OPBYTES + n * 128 + (((ks2 + (mat & 1)) ^ (n & 7)) << 4);
                uint32_t r0, r1, r2, r3;
                LDSM_X4(r0, r1, r2, r3, bd);
                fb[p * 2][0] = r0; fb[p * 2][1] = r1;
                fb[p * 2 + 1][0] = r2; fb[p * 2 + 1][1] = r3;
            }
            #pragma unroll
            for (int mt = 0; mt < 2; mt++)
                #pragma unroll
                for (int nt = 0; nt < 8; nt++)
                    MMA16816(acc[mt][nt], fa[mt], fb[nt]);
        }
        __syncthreads();
    }
    #undef ISSUE

    int qr = lane >> 2, qc = (lane & 3) << 1;
    #pragma unroll
    for (int mt = 0; mt < 2; mt++) {
        #pragma unroll
        for (int nt = 0; nt < 8; nt++) {
            int r0 = m0 + wm + mt * 16 + qr;
            int cc = n0 + wn + nt * 8 + qc;
            float a0 = acc[mt][nt][0], a1 = acc[mt][nt][1];
            float a2 = acc[mt][nt][2], a3 = acc[mt][nt][3];
            if (MODE == 0) {
                float* C = (float*)Cv;
                float2 ra = *(const float2*)(Rsd + (size_t)r0 * N + cc);
                float2 rb = *(const float2*)(Rsd + (size_t)(r0 + 8) * N + cc);
                *(float2*)(C + (size_t)r0 * N + cc)       = make_float2(a0 + ra.x, a1 + ra.y);
                *(float2*)(C + (size_t)(r0 + 8) * N + cc) = make_float2(a2 + rb.x, a3 + rb.y);
            } else {
                if (MODE == 3 && cc < 2 * D_) {
                    float invf = g_invf[(cc & (HD_ - 1)) >> 1];
                    float sn, cs;
                    sincosf((float)r0 * invf, &sn, &cs);
                    float t0 = a0 * cs - a1 * sn, t1 = a0 * sn + a1 * cs;
                    a0 = t0; a1 = t1;
                    sincosf((float)(r0 + 8) * invf, &sn, &cs);
                    t0 = a2 * cs - a3 * sn; t1 = a2 * sn + a3 * cs;
                    a2 = t0; a3 = t1;
                }
                __half* Ch = (__half*)Cv;
                *reinterpret_cast<uint32_t*>(Ch + (size_t)r0 * N + cc) =
                    packh(__float2half_rn(a0), __float2half_rn(a1));
                *reinterpret_cast<uint32_t*>(Ch + (size_t)(r0 + 8) * N + cc) =
                    packh(__float2half_rn(a2), __float2half_rn(a3));
            }
        }
    }
}

// ---------------- RMSNorm with fused fp16 output ----------------
__global__ __launch_bounds__(256) void rmsnorm_h_kernel(
    const float* __restrict__ x, const float* __restrict__ w, __half* __restrict__ oh)
{
    int row = blockIdx.x;
    const float4* xr = (const float4*)(x + (size_t)row * D_);
    float ss = 0.f;
    #pragma unroll 4
    for (int i = threadIdx.x; i < D_ / 4; i += 256) {
        float4 v = xr[i];
        ss += v.x * v.x + v.y * v.y + v.z * v.z + v.w * v.w;
    }
    __shared__ float red[8];
    #pragma unroll
    for (int o = 16; o; o >>= 1) ss += __shfl_xor_sync(0xffffffffu, ss, o);
    if ((threadIdx.x & 31) == 0) red[threadIdx.x >> 5] = ss;
    __syncthreads();
    if (threadIdx.x == 0) {
        float t = 0.f;
        #pragma unroll
        for (int i = 0; i < 8; i++) t += red[i];
        red[0] = rsqrtf(t / (float)D_ + 1e-5f);
    }
    __syncthreads();
    float inv = red[0];
    const float4* wr = (const float4*)w;
    for (int i = threadIdx.x; i < D_ / 8; i += 256) {
        float vv[8];
        float4 a = xr[2 * i], b = xr[2 * i + 1];
        float4 wa = wr[2 * i], wb = wr[2 * i + 1];
        vv[0] = a.x * inv * wa.x; vv[1] = a.y * inv * wa.y;
        vv[2] = a.z * inv * wa.z; vv[3] = a.w * inv * wa.w;
        vv[4] = b.x * inv * wb.x; vv[5] = b.y * inv * wb.y;
        vv[6] = b.z * inv * wb.z; vv[7] = b.w * inv * wb.w;
        ((uint4*)(oh + (size_t)row * D_))[i] = cvt8h(vv);
    }
}

// ---------------- HMMA flash attention: fp16 in/out, 1-term, double-buffered KV ----------------
#define ATQ 0
#define ATK(b) (32768 + (b) * 32768)
#define ATV(b) (ATK(b) + 16384)
#define ATTN3_SMEM 98304

__global__ __launch_bounds__(256, 1) void attn3_kernel(
    const __half* __restrict__ QKV, __half* __restrict__ Oh)
{
    extern __shared__ __align__(1024) char sm2[];
    const uint32_t sb = smem_to_u32(sm2);
    const int tid = threadIdx.x, wid = tid >> 5, lane = tid & 31;
    const int h = blockIdx.y;
    const int bq = gridDim.x - 1 - blockIdx.x;
    const int q0 = bq * 128;
    const int mat = lane >> 3, rin = lane & 7;

    const __half* Q  = QKV;
    const __half* Kg = QKV + D_;
    const __half* Vg = QKV + 2 * D_;

    #pragma unroll
    for (int i = 0; i < 8; i++) {
        int idx = tid + i * 256;
        int row = idx >> 4, cc = idx & 15;
        cp16(sb + ATQ + row * 256 + ((cc ^ (row & 7)) << 4),
             Q + (size_t)(q0 + row) * QKVS + h * HD_ + cc * 8);
    }
    CP_COMMIT();

    #define ISSUEKV(b, kt) do { \
        int k0_ = (kt) * 64; \
        _Pragma("unroll") \
        for (int i_ = 0; i_ < 4; i_++) { \
            int idx_ = tid + i_ * 256; \
            int row_ = idx_ >> 4, cc_ = idx_ & 15; \
            uint32_t off_ = row_ * 256 + ((cc_ ^ (row_ & 7)) << 4); \
            cp16(sb + ATK(b) + off_, Kg + (size_t)(k0_ + row_) * QKVS + h * HD_ + cc_ * 8); \
            cp16(sb + ATV(b) + off_, Vg + (size_t)(k0_ + row_) * QKVS + h * HD_ + cc_ * 8); \
        } \
    } while (0)

    const int nk = q0 / 64 + 2;
    ISSUEKV(0, 0); CP_COMMIT();

    float m0 = -1e30f, m1 = -1e30f, l0 = 0.f, l1 = 0.f;
    float oacc[16][4] = {};
    const int g0r = q0 + wid * 16 + (lane >> 2);
    const int g1r = g0r + 8;

    for (int kt = 0; kt < nk; kt++) {
        if (kt + 1 < nk) { ISSUEKV((kt + 1) & 1, kt + 1); CP_COMMIT(); CP_WAIT(1); }
        else            { CP_WAIT(0); }
        __syncthreads();
        int k0 = kt * 64;
        int buf = kt & 1;

        float sacc[8][4] = {};
        #pragma unroll
        for (int kk = 0; kk < 8; kk++) {
            int kk2 = kk << 1;
            int m = wid * 16 + ((mat & 1) << 3) + rin;
            uint32_t ad = sb + ATQ + m * 256 + (((kk2 + (mat >> 1)) ^ (m & 7)) << 4);
            uint32_t qa[4];
            LDSM_X4(qa[0], qa[1], qa[2], qa[3], ad);
            #pragma unroll
            for (int nt = 0; nt < 4; nt++) {
                int n = nt * 16 + ((mat >> 1) << 3) + rin;
                uint32_t bd = sb + ATK(buf) + n * 256 + (((kk2 + (mat & 1)) ^ (n & 7)) << 4);
                uint32_t b0, b1, b2, b3;
                LDSM_X4(b0, b1, b2, b3, bd);
                MMA4(sacc[2 * nt],     qa[0], qa[1], qa[2], qa[3], b0, b1);
                MMA4(sacc[2 * nt + 1], qa[0], qa[1], qa[2], qa[3], b2, b3);
            }
        }

        if (k0 + 63 > g0r) {
            #pragma unroll
            for (int nt = 0; nt < 8; nt++) {
                int c0 = k0 + nt * 8 + ((lane & 3) << 1);
                if (c0     > g0r) sacc[nt][0] = -1e30f;
                if (c0 + 1 > g0r) sacc[nt][1] = -1e30f;
                if (c0     > g1r) sacc[nt][2] = -1e30f;
                if (c0 + 1 > g1r) sacc[nt][3] = -1e30f;
            }
        }

        float mx0 = m0, mx1 = m1;
        #pragma unroll
        for (int nt = 0; nt < 8; nt++) {
            mx0 = fmaxf(mx0, fmaxf(sacc[nt][0], sacc[nt][1]));
            mx1 = fmaxf(mx1, fmaxf(sacc[nt][2], sacc[nt][3]));
        }
        mx0 = fmaxf(mx0, __shfl_xor_sync(0xffffffffu, mx0, 1));
        mx0 = fmaxf(mx0, __shfl_xor_sync(0xffffffffu, mx0, 2));
        mx1 = fmaxf(mx1, __shfl_xor_sync(0xffffffffu, mx1, 1));
        mx1 = fmaxf(mx1, __shfl_xor_sync(0xffffffffu, mx1, 2));
        float al0 = __expf(m0 - mx0), al1 = __expf(m1 - mx1);
        m0 = mx0; m1 = mx1;
        float rs0 = 0.f, rs1 = 0.f;
        uint32_t ph0[8], ph1[8];
        #pragma unroll
        for (int nt = 0; nt < 8; nt++) {
            float p0 = __expf(sacc[nt][0] - mx0);
            float p1 = __expf(sacc[nt][1] - mx0);
            float p2 = __expf(sacc[nt][2] - mx1);
            float p3 = __expf(sacc[nt][3] - mx1);
            rs0 += p0 + p1; rs1 += p2 + p3;
            ph0[nt] = packh(__float2half_rn(p0), __float2half_rn(p1));
            ph1[nt] = packh(__float2half_rn(p2), __float2half_rn(p3));
        }
        rs0 += __shfl_xor_sync(0xffffffffu, rs0, 1);
        rs0 += __shfl_xor_sync(0xffffffffu, rs0, 2);
        rs1 += __shfl_xor_sync(0xffffffffu, rs1, 1);
        rs1 += __shfl_xor_sync(0xffffffffu, rs1, 2);
        l0 = l0 * al0 + rs0;
        l1 = l1 * al1 + rs1;
        #pragma unroll
        for (int t = 0; t < 16; t++) {
            oacc[t][0] *= al0; oacc[t][1] *= al0;
            oacc[t][2] *= al1; oacc[t][3] *= al1;
        }

        #pragma unroll
        for (int kk = 0; kk < 4; kk++) {
            uint32_t a0 = ph0[2 * kk], a1 = ph1[2 * kk], a2 = ph0[2 * kk + 1], a3 = ph1[2 * kk + 1];
            #pragma unroll
            for (int ntp = 0; ntp < 8; ntp++) {
                int vrow = kk * 16 + rin + ((mat >> 1) << 3);
                int vch  = 2 * ntp + (mat & 1);
                uint32_t vd = sb + ATV(buf) + vrow * 256 + ((vch ^ (vrow & 7)) << 4);
                uint32_t r0, r1, r2, r3;
                LDSM_X4_T(r0, r1, r2, r3, vd);
                MMA4(oacc[2 * ntp],     a0, a1, a2, a3, r0, r2);
                MMA4(oacc[2 * ntp + 1], a0, a1, a2, a3, r1, r3);
            }
        }
        __syncthreads();
    }
    #undef ISSUEKV

    float i0 = 1.f / l0, i1 = 1.f / l1;
    #pragma unroll
    for (int t = 0; t < 16; t++) {
        int col = h * HD_ + t * 8 + ((lane & 3) << 1);
        *reinterpret_cast<uint32_t*>(Oh + (size_t)g0r * D_ + col) =
            packh(__float2half_rn(oacc[t][0] * i0), __float2half_rn(oacc[t][1] * i0));
        *reinterpret_cast<uint32_t*>(Oh + (size_t)g1r * D_ + col) =
            packh(__float2half_rn(oacc[t][2] * i1), __float2half_rn(oacc[t][3] * i1));
    }
}

// ---------------- SiLU(gate) * up from merged [S, gate|up] ----------------
__global__ void silu_h_kernel(const __half* __restrict__ gu, __half* __restrict__ oh, int n8)
{
    int i = blockIdx.x * blockDim.x + threadIdx.x;
    if (i < n8) {
        int row = i / (FF_ / 8);
        int rem = i - row * (FF_ / 8);
        const __half* gp8 = gu + (size_t)row * GUS + rem * 8;
        uint4 gv = *(const uint4*)gp8;
        uint4 uv = *(const uint4*)(gp8 + FF_);
        const uint32_t* gp = &gv.x;
        const uint32_t* up = &uv.x;
        float vv[8];
        #pragma unroll
        for (int j = 0; j < 4; j++) {
            float2 gf = __half22float2(*reinterpret_cast<const __half2*>(&gp[j]));
            float2 uf = __half22float2(*reinterpret_cast<const __half2*>(&up[j]));
            vv[2 * j]     = gf.x / (1.f + __expf(-gf.x)) * uf.x;
            vv[2 * j + 1] = gf.y / (1.f + __expf(-gf.y)) * uf.y;
        }
        ((uint4*)oh)[i] = cvt8h(vv);
    }
}

// ---------------- launch ----------------
extern "C" void kernel_launch(void* const* d_in, const int* in_sizes, int n_in,
                              void* d_out, int out_size)
{
    const float* x      = (const float*)d_in[0];
    const float* ln_w   = (const float*)d_in[1];
    const float* ffln_w = (const float*)d_in[2];
    const float* wq     = (const float*)d_in[3];
    const float* wk     = (const float*)d_in[4];
    const float* wv     = (const float*)d_in[5];
    const float* wo     = (const float*)d_in[6];
    const float* wg     = (const float*)d_in[7];
    const float* w1     = (const float*)d_in[8];
    const float* w2     = (const float*)d_in[9];
    float* out = (float*)d_out;

    float* x2;
    cudaGetSymbolAddress((void**)&x2, g_x2);

    __half *qkvh, *guh, *ah;
    cudaGetSymbolAddress((void**)&qkvh, g_qkvh);
    cudaGetSymbolAddress((void**)&guh,  g_guh);
    cudaGetSymbolAddress((void**)&ah,   g_ah);

    __half *wqkvt, *wgut, *wot, *w2t;
    cudaGetSymbolAddress((void**)&wqkvt, g_wqkvt);
    cudaGetSymbolAddress((void**)&wgut,  g_wgut);
    cudaGetSymbolAddress((void**)&wot,   g_wot);
    cudaGetSymbolAddress((void**)&w2t,   g_w2t);

    cudaFuncSetAttribute(attn3_kernel, cudaFuncAttributeMaxDynamicSharedMemorySize, ATTN3_SMEM);
    cudaFuncSetAttribute(hgemm<0>, cudaFuncAttributeMaxDynamicSharedMemorySize, HGEMM_SMEM);
    cudaFuncSetAttribute(hgemm<1>, cudaFuncAttributeMaxDynamicSharedMemorySize, HGEMM_SMEM);
    cudaFuncSetAttribute(hgemm<3>, cudaFuncAttributeMaxDynamicSharedMemorySize, HGEMM_SMEM);

    // init inv_freq table
    rope_init_kernel<<<1, HD_ / 2>>>();

    // weight prep into merged buffers (wq carries 1/sqrt(HD))
    const float qscale = 0.08838834764831845f;
    wconv2_kernel<<<dim3(D_ / 32, D_ / 64), 256>>>(wq, wqkvt,                       D_, D_, qscale);
    wconv2_kernel<<<dim3(D_ / 32, D_ / 64), 256>>>(wk, wqkvt + (size_t)D_ * D_,     D_, D_, 1.f);
    wconv2_kernel<<<dim3(D_ / 32, D_ / 64), 256>>>(wv, wqkvt + (size_t)2 * D_ * D_, D_, D_, 1.f);
    wconv2_kernel<<<dim3(D_ / 32, D_ / 64), 256>>>(wo, wot, D_, D_, 1.f);
    wconv2_kernel<<<dim3(FF_ / 32, D_ / 64), 256>>>(wg, wgut,                      D_, FF_, 1.f);
    wconv2_kernel<<<dim3(FF_ / 32, D_ / 64), 256>>>(w1, wgut + (size_t)FF_ * D_,   D_, FF_, 1.f);
    wconv2_kernel<<<dim3(D_ / 32, FF_ / 64), 256>>>(w2, w2t, FF_, D_, 1.f);

    // xn = rmsnorm(x) -> ah
    rmsnorm_h_kernel<<<S_, 256>>>(x, ln_w, ah);

    // merged qkv projection with fused RoPE (one N=12288 GEMM)
    hgemm<3><<<dim3(S_ / 128, QKVS / 128), 256, HGEMM_SMEM>>>(
        S_, QKVS, D_, ah, wqkvt, nullptr, qkvh);

    // attention (O -> ah)
    attn3_kernel<<<dim3(S_ / 128, H_), 256, ATTN3_SMEM>>>(qkvh, ah);

    // x2 = attn @ wo + x   (fp32 out)
    hgemm<0><<<dim3(S_ / 128, D_ / 128), 256, HGEMM_SMEM>>>(
        S_, D_, D_, ah, wot, x, x2);

    // xn2 = rmsnorm(x2) -> ah
    rmsnorm_h_kernel<<<S_, 256>>>(x2, ffln_w, ah);

    // merged gate|up projection (one N=22016 GEMM)
    hgemm<1><<<dim3(S_ / 128, GUS / 128), 256, HGEMM_SMEM>>>(
        S_, GUS, D_, ah, wgut, nullptr, guh);

    // h = silu(gate) * up -> ah
    int n8 = (S_ * FF_) / 8;
    silu_h_kernel<<<(n8 + 255) / 256, 256>>>(guh, ah, n8);

    // out = h @ w2 + x2  (fp32 out)
    hgemm<0><<<dim3(S_ / 128, D_ / 128), 256, HGEMM_SMEM>>>(
        S_, D_, FF_, ah, w2t, x2, out);
}